// round 8
// baseline (speedup 1.0000x reference)
#include <cuda_runtime.h>

#define H 512
#define B 128
#define T 1024
#define NCLS 10

#define GRID 128
#define TPB 128
#define BT 32
#define JT 16
#define ROWP 68                   // padded h smem row stride (floats), 16B-aligned
#define WSM_FLOATS (4*256*32)     // 32768  (128 KB)
#define HSM_FLOATS (256*ROWP)     // 17408  (68 KB)
#define SMEM_BYTES ((WSM_FLOATS + HSM_FLOATS)*4)   // 200704

typedef unsigned long long ull;

// ---------------- device scratch (static, no allocation) ----------------
__device__ float g_xT[T * B];                // transposed x [t][b]
__device__ float g_hp[2][256 * B * 2];       // packed h: [k2][b][kbit]
__device__ unsigned g_cnt4[4];
__device__ unsigned g_gen4[4];

// ---------------- helpers ----------------
__device__ __forceinline__ ull fma2(ull a, ull b, ull c) {
    ull d;
    asm("fma.rn.f32x2 %0, %1, %2, %3;" : "=l"(d) : "l"(a), "l"(b), "l"(c));
    return d;
}
__device__ __forceinline__ float hadd2(ull a) {
    union { ull u; float2 f; } x; x.u = a;
    return x.f.x + x.f.y;
}
__device__ __forceinline__ float sigf(float x) {
    return __fdividef(1.0f, 1.0f + __expf(-x));
}
__device__ __forceinline__ float tanf_(float x) {
    return __fdividef(2.0f, 1.0f + __expf(-2.0f * x)) - 1.0f;
}

// group barrier: 32 blocks sharing bt; monotone generation targets
__device__ __forceinline__ void gbar(unsigned* cnt, unsigned* gen, unsigned target) {
    __syncthreads();
    if (threadIdx.x == 0) {
        unsigned old;
        asm volatile("atom.add.acq_rel.gpu.global.u32 %0, [%1], 1;"
                     : "=r"(old) : "l"(cnt) : "memory");
        if (old == 31u) {
            asm volatile("st.relaxed.gpu.global.u32 [%0], %1;"
                         :: "l"(cnt), "r"(0u) : "memory");
            asm volatile("st.release.gpu.global.u32 [%0], %1;"
                         :: "l"(gen), "r"(target) : "memory");
        } else {
            unsigned v;
            do {
                asm volatile("ld.acquire.gpu.global.u32 %0, [%1];"
                             : "=r"(v) : "l"(gen) : "memory");
            } while (v < target);
        }
    }
    __syncthreads();
}

// ---------------- single fused persistent kernel ----------------
__global__ void __launch_bounds__(TPB, 1)
lstm_fused(const float* __restrict__ x,
           const float* __restrict__ Wgx, const float* __restrict__ Wgh, const float* __restrict__ bg,
           const float* __restrict__ Wix, const float* __restrict__ Wih, const float* __restrict__ bi,
           const float* __restrict__ Wfx, const float* __restrict__ Wfh, const float* __restrict__ bf,
           const float* __restrict__ Wox, const float* __restrict__ Woh, const float* __restrict__ bo,
           const float* __restrict__ Wph, const float* __restrict__ bp,
           float* __restrict__ out) {
    extern __shared__ float smem[];
    float* Wsm = smem;                 // [g][k2][j*2 + kbit]   rows of 32 floats (128B)
    float* hsm = smem + WSM_FLOATS;    // [k2][bl*2 + kbit]     rows of 64 floats, stride ROWP

    const int tid  = threadIdx.x;
    const int warp = tid >> 5;
    const int lane = tid & 31;
    const int bt   = blockIdx.x >> 5;      // 0..3 (barrier group = b-slice)
    const int jt   = blockIdx.x & 31;      // 0..31
    const int b0b  = bt * BT;
    const int j0b  = jt * JT;
    const int bgrp = (warp << 2) | (lane >> 3);   // 0..15
    const int jgrp = lane & 7;                    // 0..7
    const int b0   = b0b + 2 * bgrp;              // this thread's 2 batches
    const int j0   = j0b + 2 * jgrp;              // this thread's 2 hidden cols

    unsigned* cnt = &g_cnt4[bt];
    unsigned* gen = &g_gen4[bt];

    // ---- phase 0a: transpose x slice (t in [jt*32, jt*32+32), b in this group's slice) ----
#pragma unroll
    for (int i = 0; i < 8; i++) {
        int idx = tid + i * TPB;               // 0..1023
        int tt  = jt * 32 + (idx >> 5);
        int bb  = b0b + (idx & 31);
        g_xT[tt * B + bb] = x[(size_t)bb * T + tt];
    }

    // ---- phase 0b: pack recurrent W tile into smem: Wsm[g][k2][jl*2 + (k&1)] ----
#pragma unroll
    for (int g = 0; g < 4; g++) {
        const float* S = (g == 0) ? Wgh : (g == 1) ? Wih : (g == 2) ? Wfh : Woh;
#pragma unroll
        for (int i = 0; i < 64; i++) {
            int idx = tid + i * TPB;           // 0..8191
            int k   = idx >> 4;                // 0..511
            int jl  = idx & 15;                // 0..15
            Wsm[(g * 256 + (k >> 1)) * 32 + jl * 2 + (k & 1)] = S[k * H + j0b + jl];
        }
    }

    // per-thread input-projection weights / biases for 2 j's x 4 gates
    float wxv[2][4], bv[2][4];
#pragma unroll
    for (int ji = 0; ji < 2; ji++) {
        int j = j0 + ji;
        wxv[ji][0] = Wgx[j]; wxv[ji][1] = Wix[j]; wxv[ji][2] = Wfx[j]; wxv[ji][3] = Wox[j];
        bv[ji][0]  = bg[j];  bv[ji][1]  = bi[j];  bv[ji][2]  = bf[j];  bv[ji][3]  = bo[j];
    }

    const float* hload = hsm + 4 * bgrp;              // + k2*ROWP
    const float* wload = Wsm + 4 * jgrp;              // + (g*256+k2)*32
    const int    hk2   = (j0 >> 1);                   // packed row this thread writes

    float c00 = 0.f, c01 = 0.f, c10 = 0.f, c11 = 0.f; // c[b][j]

    gbar(cnt, gen, 1u);   // xT visible group-wide; Wsm via the internal syncthreads

    for (int t = 0; t < T; t++) {
        float p[16];

        if (t > 0) {
            const float* hread = g_hp[t & 1];
            // --- stage packed h rows (ALL 256 rows x 64-float slice) into smem ---
            {
#pragma unroll
                for (int i = 0; i < 32; i++) {
                    int idx  = tid + i * TPB;          // 0..4095 float4
                    int row  = idx >> 4;               // 0..255
                    int c16  = idx & 15;
                    float4 v = __ldcg((const float4*)(hread + row * (B * 2) + b0b * 2) + c16);
                    *(float4*)(hsm + row * ROWP + c16 * 4) = v;
                }
            }
            __syncthreads();

            // --- GEMM: 2b x 2j x 4g, f32x2 over k-pairs, 1-phase LDS ---
            ull acc[16];       // [g*4 + bi*2 + ji]
#pragma unroll
            for (int i = 0; i < 16; i++) acc[i] = 0ull;

#pragma unroll 8
            for (int k2 = 0; k2 < 256; k2++) {
                ulonglong2 hv = *(const ulonglong2*)(hload + k2 * ROWP);
#pragma unroll
                for (int g = 0; g < 4; g++) {
                    ulonglong2 wv = *(const ulonglong2*)(wload + (g * 256 + k2) * 32);
                    acc[g * 4 + 0] = fma2(hv.x, wv.x, acc[g * 4 + 0]);  // b0,j0
                    acc[g * 4 + 1] = fma2(hv.x, wv.y, acc[g * 4 + 1]);  // b0,j1
                    acc[g * 4 + 2] = fma2(hv.y, wv.x, acc[g * 4 + 2]);  // b1,j0
                    acc[g * 4 + 3] = fma2(hv.y, wv.y, acc[g * 4 + 3]);  // b1,j1
                }
            }
#pragma unroll
            for (int i = 0; i < 16; i++) p[i] = hadd2(acc[i]);
        } else {
#pragma unroll
            for (int i = 0; i < 16; i++) p[i] = 0.f;
        }

        const float2 xv = *(const float2*)(g_xT + t * B + b0);

        // epilogue: 4 complete LSTM cells per thread (all gates local)
        float h00, h01, h10, h11;
        {
            float gv = tanf_(p[0]  + xv.x * wxv[0][0] + bv[0][0]);
            float iv = sigf (p[4]  + xv.x * wxv[0][1] + bv[0][1]);
            float fv = sigf (p[8]  + xv.x * wxv[0][2] + bv[0][2]);
            float ov = sigf (p[12] + xv.x * wxv[0][3] + bv[0][3]);
            c00 = gv * iv + c00 * fv;  h00 = tanf_(c00) * ov;
        }
        {
            float gv = tanf_(p[1]  + xv.x * wxv[1][0] + bv[1][0]);
            float iv = sigf (p[5]  + xv.x * wxv[1][1] + bv[1][1]);
            float fv = sigf (p[9]  + xv.x * wxv[1][2] + bv[1][2]);
            float ov = sigf (p[13] + xv.x * wxv[1][3] + bv[1][3]);
            c01 = gv * iv + c01 * fv;  h01 = tanf_(c01) * ov;
        }
        {
            float gv = tanf_(p[2]  + xv.y * wxv[0][0] + bv[0][0]);
            float iv = sigf (p[6]  + xv.y * wxv[0][1] + bv[0][1]);
            float fv = sigf (p[10] + xv.y * wxv[0][2] + bv[0][2]);
            float ov = sigf (p[14] + xv.y * wxv[0][3] + bv[0][3]);
            c10 = gv * iv + c10 * fv;  h10 = tanf_(c10) * ov;
        }
        {
            float gv = tanf_(p[3]  + xv.y * wxv[1][0] + bv[1][0]);
            float iv = sigf (p[7]  + xv.y * wxv[1][1] + bv[1][1]);
            float fv = sigf (p[11] + xv.y * wxv[1][2] + bv[1][2]);
            float ov = sigf (p[15] + xv.y * wxv[1][3] + bv[1][3]);
            c11 = gv * iv + c11 * fv;  h11 = tanf_(c11) * ov;
        }

        // packed h write: one STG.128 = (b0:j0,j1, b0+1:j0,j1) at row j0>>1
        {
            float* hwrite = g_hp[(t + 1) & 1];
            *(float4*)(hwrite + hk2 * (B * 2) + b0 * 2) = make_float4(h00, h01, h10, h11);
        }

        gbar(cnt, gen, (unsigned)(t + 2));
    }

    // ---- final projection for b_out (within this group's b-slice; h visible post-gbar) ----
    {
        const int b_out = b0b + jt;
        const float* hp0 = g_hp[0];               // T even -> final state in buffer 0
        float2 hv[8];
#pragma unroll
        for (int i = 0; i < 8; i++) {
            int k2 = lane + 32 * i;
            hv[i] = *(const float2*)(hp0 + k2 * (B * 2) + b_out * 2);
        }
        for (int ccl = warp; ccl < NCLS; ccl += 4) {
            const float* wr = Wph + ccl * H;
            float s = 0.f;
#pragma unroll
            for (int i = 0; i < 8; i++) {
                int k2 = lane + 32 * i;
                s += hv[i].x * wr[2 * k2] + hv[i].y * wr[2 * k2 + 1];
            }
#pragma unroll
            for (int off = 16; off; off >>= 1) s += __shfl_down_sync(0xffffffffu, s, off);
            if (lane == 0) out[b_out * NCLS + ccl] = s + bp[ccl];
        }
    }

    // ---- reset group counters for the next graph replay ----
    __syncthreads();
    if (tid == 0) {
        unsigned old = atomicAdd(cnt, 1u);
        if (old == 31u) {
            asm volatile("st.relaxed.gpu.global.u32 [%0], %1;"
                         :: "l"(cnt), "r"(0u) : "memory");
            asm volatile("st.relaxed.gpu.global.u32 [%0], %1;"
                         :: "l"(gen), "r"(0u) : "memory");
        }
    }
}

// ---------------- launch ----------------
extern "C" void kernel_launch(void* const* d_in, const int* in_sizes, int n_in,
                              void* d_out, int out_size) {
    const float* x   = (const float*)d_in[0];
    const float* Wgx = (const float*)d_in[1];
    const float* Wgh = (const float*)d_in[2];
    const float* bg  = (const float*)d_in[3];
    const float* Wix = (const float*)d_in[4];
    const float* Wih = (const float*)d_in[5];
    const float* bi  = (const float*)d_in[6];
    const float* Wfx = (const float*)d_in[7];
    const float* Wfh = (const float*)d_in[8];
    const float* bf  = (const float*)d_in[9];
    const float* Wox = (const float*)d_in[10];
    const float* Woh = (const float*)d_in[11];
    const float* bo  = (const float*)d_in[12];
    const float* Wph = (const float*)d_in[13];
    const float* bp  = (const float*)d_in[14];
    float* out = (float*)d_out;

    cudaFuncSetAttribute(lstm_fused, cudaFuncAttributeMaxDynamicSharedMemorySize,
                         SMEM_BYTES);

    lstm_fused<<<GRID, TPB, SMEM_BYTES>>>(x,
        Wgx, Wgh, bg, Wix, Wih, bi, Wfx, Wfh, bf, Wox, Woh, bo, Wph, bp, out);
}